// round 5
// baseline (speedup 1.0000x reference)
#include <cuda_runtime.h>
#include <cuda_bf16.h>
#include <stdint.h>

#define DDIM   2048
#define TILE_M 128
#define TILE_N 256
#define TILE_K 64                    // int8 elements per k-stage (64 bytes/row)
#define NKS    (DDIM / TILE_K)       // 32 k-stages
#define STAGES 5
#define NMAX   16384
#define CMAX   8192

#define A_BLK  (TILE_M * TILE_K)     // 8192 bytes per (m-tile, k-stage)
#define B_BLK  (TILE_N * TILE_K)     // 16384 bytes
#define SLOT   (A_BLK + B_BLK)       // 24576
#define SMEM_BYTES (1024 + STAGES * SLOT)   // 123904

// Packed, pre-swizzled int8 operands + per-row dequant scales
__device__ __align__(1024) char g_fn[(size_t)NMAX * DDIM];   // 32 MB
__device__ __align__(1024) char g_pn[(size_t)CMAX * DDIM];   // 16 MB
__device__ float g_fs[NMAX];
__device__ float g_ps[CMAX];

// ------------------------------ PTX helpers -----------------------------
__device__ __forceinline__ uint32_t smem_u32(const void* p) {
  uint32_t a;
  asm("{ .reg .u64 t; cvta.to.shared.u64 t, %1; cvt.u32.u64 %0, t; }" : "=r"(a) : "l"(p));
  return a;
}

#define MBAR_INIT(a, c) asm volatile("mbarrier.init.shared.b64 [%0], %1;" :: "r"(a), "r"(c) : "memory")
#define MBAR_ARRIVE(a)  asm volatile("mbarrier.arrive.shared.b64 _, [%0];" :: "r"(a) : "memory")
#define MBAR_EXPECT_TX(a, n) \
  asm volatile("mbarrier.arrive.expect_tx.shared.b64 _, [%0], %1;" :: "r"(a), "r"(n) : "memory")

#define MBAR_WAIT(a, par) do {                                                              \
  uint32_t _m = (a); uint32_t _p = (par); uint32_t _ok;                                     \
  asm volatile("{\n\t.reg .pred p;\n\t"                                                     \
    "mbarrier.try_wait.parity.acquire.cta.shared::cta.b64 p, [%1], %2;\n\t"                 \
    "selp.b32 %0, 1, 0, p;\n\t}" : "=r"(_ok) : "r"(_m), "r"(_p) : "memory");                \
  if (!_ok) {                                                                               \
    asm volatile("{\n\t.reg .pred P1;\n\t"                                                  \
      "WL_%=:\n\t"                                                                          \
      "mbarrier.try_wait.parity.acquire.cta.shared::cta.b64 P1, [%0], %1, 0x989680;\n\t"    \
      "@P1 bra.uni WD_%=;\n\t"                                                              \
      "bra.uni WL_%=;\n\t"                                                                  \
      "WD_%=:\n\t}" :: "r"(_m), "r"(_p) : "memory");                                        \
  }                                                                                         \
} while (0)

// non-tensor bulk copy gmem -> smem with transaction-count completion (sm_90, non-a)
__device__ __forceinline__ void bulk_g2s(uint32_t dst, const void* src, uint32_t bytes,
                                         uint32_t mbar) {
  asm volatile(
    "cp.async.bulk.shared::cluster.global.mbarrier::complete_tx::bytes [%0], [%1], %2, [%3];"
    :: "r"(dst), "l"(src), "r"(bytes), "r"(mbar) : "memory");
}

__device__ __forceinline__ void ldmx4(uint32_t* r, uint32_t addr) {
  asm volatile("ldmatrix.sync.aligned.m8n8.x4.shared.b16 {%0,%1,%2,%3}, [%4];"
               : "=r"(r[0]), "=r"(r[1]), "=r"(r[2]), "=r"(r[3]) : "r"(addr));
}

// s8 IMMA: D[s32] += A(16x32) * B(32x8)^T — byte-layout identical to bf16 16816
__device__ __forceinline__ void mma16832(int* d, const uint32_t* a, uint32_t b0, uint32_t b1) {
  asm volatile(
    "mma.sync.aligned.m16n8k32.row.col.s32.s8.s8.s32 "
    "{%0,%1,%2,%3}, {%4,%5,%6,%7}, {%8,%9}, {%0,%1,%2,%3};"
    : "+r"(d[0]), "+r"(d[1]), "+r"(d[2]), "+r"(d[3])
    : "r"(a[0]), "r"(a[1]), "r"(a[2]), "r"(a[3]), "r"(b0), "r"(b1));
}

// --------------------------- normalize + quantize + pack ----------------
// One block per row. Packed layout per (row-tile mt, k-stage kt): contiguous
// tile_rows*64B block; row rm holds its 64-int8 k-slice as 4 16B chunks,
// chunk c at position c ^ ((rm>>1)&3) (conflict-free for ldmatrix).
__device__ __forceinline__ void packq(char* rowbase, int t2, float4 v, float qs,
                                      size_t bstride, uint32_t s) {
  int a = __float2int_rn(v.x * qs);
  int b = __float2int_rn(v.y * qs);
  int c = __float2int_rn(v.z * qs);
  int d = __float2int_rn(v.w * qs);
  uint32_t u = (uint32_t)(a & 0xFF) | ((uint32_t)(b & 0xFF) << 8) |
               ((uint32_t)(c & 0xFF) << 16) | ((uint32_t)(d & 0xFF) << 24);
  const int kt = t2 >> 4;                       // 16 threads-worth (64 floats) per stage
  const uint32_t cp = ((uint32_t)t2 >> 2) & 3;  // 16B chunk within stage
  const uint32_t byo = ((uint32_t)t2 & 3) * 4;
  *reinterpret_cast<uint32_t*>(rowbase + (size_t)kt * bstride + ((cp ^ s) << 4) + byo) = u;
}

__global__ void norm_pack_kernel(const float* __restrict__ src, char* __restrict__ dst,
                                 float* __restrict__ rowscale, int tile_rows) {
  const int row = blockIdx.x;
  const int tid = threadIdx.x;
  const float4* s4 = reinterpret_cast<const float4*>(src + (size_t)row * DDIM);
  float4 v0 = s4[tid];
  float4 v1 = s4[tid + 256];
  float acc = v0.x * v0.x + v0.y * v0.y + v0.z * v0.z + v0.w * v0.w
            + v1.x * v1.x + v1.y * v1.y + v1.z * v1.z + v1.w * v1.w;
  float mx = fmaxf(fmaxf(fmaxf(fabsf(v0.x), fabsf(v0.y)), fmaxf(fabsf(v0.z), fabsf(v0.w))),
                   fmaxf(fmaxf(fabsf(v1.x), fabsf(v1.y)), fmaxf(fabsf(v1.z), fabsf(v1.w))));
#pragma unroll
  for (int o = 16; o > 0; o >>= 1) {
    acc += __shfl_xor_sync(0xFFFFFFFFu, acc, o);
    mx = fmaxf(mx, __shfl_xor_sync(0xFFFFFFFFu, mx, o));
  }
  __shared__ float redS[8], redM[8];
  if ((tid & 31) == 0) { redS[tid >> 5] = acc; redM[tid >> 5] = mx; }
  __syncthreads();
  float tot = 0.f, mall = 0.f;
#pragma unroll
  for (int i = 0; i < 8; i++) { tot += redS[i]; mall = fmaxf(mall, redM[i]); }
  const float sc = 1.0f / fmaxf(sqrtf(tot), 1e-12f);
  const float mxn = fmaxf(mall * sc, 1e-30f);   // max |normalized element|
  const float qs = 127.0f / mxn;

  if (tid == 0) rowscale[row] = mxn * (1.0f / 127.0f);

  const int mt = row / tile_rows;
  const int rm = row % tile_rows;
  const size_t bstride = (size_t)tile_rows * 64;
  char* rowbase = dst + (size_t)mt * NKS * bstride + (size_t)rm * 64;
  const uint32_t s = ((uint32_t)rm >> 1) & 3;
  float4 n0 = make_float4(v0.x * sc, v0.y * sc, v0.z * sc, v0.w * sc);
  float4 n1 = make_float4(v1.x * sc, v1.y * sc, v1.z * sc, v1.w * sc);
  packq(rowbase, tid, n0, qs, bstride, s);
  packq(rowbase, tid + 256, n1, qs, bstride, s);
}

// --------------------------- GEMM + distance ----------------------------
// CTA tile 128x256, 8 warps in 2(M) x 4(N), warp tile 64x64, mma m16n8k32 s8.
__global__ __launch_bounds__(256, 1)
void gemm_dist_kernel(const char* __restrict__ Apk, const char* __restrict__ Bpk,
                      const float* __restrict__ rsF, const float* __restrict__ rsP,
                      const float* __restrict__ dscale,
                      float* __restrict__ out, int Crows) {
  extern __shared__ __align__(1024) char smem[];
  const uint32_t sb = smem_u32(smem);
  const int tid = threadIdx.x;
  const int wid = tid >> 5;
  const int lane = tid & 31;

  // supertile mapping: groups of 4 m-tiles x all n-tiles keep B L2-resident
  const int nt = Crows / TILE_N;                 // 32
  const int per_sg = 4 * nt;                     // 128
  const int sg = blockIdx.x / per_sg;
  const int r = blockIdx.x % per_sg;
  const int m_tile = sg * 4 + (r & 3);
  const int n_tile = r >> 2;

  const char* Abase = Apk + (size_t)m_tile * NKS * A_BLK;
  const char* Bbase = Bpk + (size_t)n_tile * NKS * B_BLK;

  // barriers: full[s] @ sb + s*8 ; empty[s] @ sb + 64 + s*8
  if (tid == 0) {
#pragma unroll
    for (int s = 0; s < STAGES; s++) {
      MBAR_INIT(sb + s * 8, 1);
      MBAR_INIT(sb + 64 + s * 8, 8);
    }
  }
  __syncthreads();

  if (tid == 0) {
#pragma unroll
    for (int t = 0; t < STAGES - 1; t++) {
      const uint32_t full = sb + t * 8;
      const uint32_t slot = sb + 1024 + t * SLOT;
      MBAR_EXPECT_TX(full, SLOT);
      bulk_g2s(slot, Abase + (size_t)t * A_BLK, A_BLK, full);
      bulk_g2s(slot + A_BLK, Bbase + (size_t)t * B_BLK, B_BLK, full);
    }
  }

  // per-lane ldmatrix addressing constants (byte layout same as bf16 version)
  const int wm = wid & 1;
  const int wn = wid >> 1;
  const uint32_t sA = (((uint32_t)lane & 15) >> 1) & 3;
  const uint32_t sB = (((uint32_t)lane & 7) >> 1) & 3;
  const uint32_t aRowOff = (uint32_t)(wm * 64 + (lane & 15)) * 64;
  const uint32_t aChunkHalf = (uint32_t)(lane >> 4);
  const uint32_t bRowOff = (uint32_t)(wn * 64 + (lane >> 4) * 8 + (lane & 7)) * 64;
  const uint32_t bChunkHalf = ((uint32_t)lane >> 3) & 1;

  int acc[4][8][4];
#pragma unroll
  for (int i = 0; i < 4; i++)
#pragma unroll
    for (int j = 0; j < 8; j++)
#pragma unroll
      for (int c = 0; c < 4; c++) acc[i][j][c] = 0;

  for (int i = 0; i < NKS; i++) {
    const int t = i + STAGES - 1;
    if (t < NKS && tid == 0) {
      const int ts = t % STAGES;
      MBAR_WAIT(sb + 64 + ts * 8, ((t / STAGES) - 1) & 1);      // slot free
      const uint32_t full = sb + ts * 8;
      const uint32_t slot = sb + 1024 + ts * SLOT;
      MBAR_EXPECT_TX(full, SLOT);
      bulk_g2s(slot, Abase + (size_t)t * A_BLK, A_BLK, full);
      bulk_g2s(slot + A_BLK, Bbase + (size_t)t * B_BLK, B_BLK, full);
    }

    const int is = i % STAGES;
    MBAR_WAIT(sb + is * 8, (i / STAGES) & 1);                   // data ready
    const uint32_t slot = sb + 1024 + is * SLOT;

#pragma unroll
    for (int ks = 0; ks < 2; ks++) {                            // 2 x k=32 per stage
      uint32_t a[4][4], b[4][4];
      const uint32_t ca = (((uint32_t)ks * 2 + aChunkHalf) ^ sA) << 4;
      const uint32_t cb = (((uint32_t)ks * 2 + bChunkHalf) ^ sB) << 4;
#pragma unroll
      for (int ii = 0; ii < 4; ii++) ldmx4(a[ii], slot + aRowOff + ii * 1024 + ca);
#pragma unroll
      for (int jp = 0; jp < 4; jp++) ldmx4(b[jp], slot + A_BLK + bRowOff + jp * 1024 + cb);
#pragma unroll
      for (int ii = 0; ii < 4; ii++)
#pragma unroll
        for (int j = 0; j < 8; j++)
          mma16832(acc[ii][j], a[ii], b[j >> 1][(j & 1) * 2], b[j >> 1][(j & 1) * 2 + 1]);
    }

    __syncwarp();
    if (lane == 0) MBAR_ARRIVE(sb + 64 + is * 8);               // slot consumed
  }

  // fused dequant + distance epilogue
  const float sc = fabsf(dscale[0]);
  const int g = lane >> 2;
  const int tq = lane & 3;
  const int m0 = m_tile * TILE_M + wm * 64 + g;
  const int nb = n_tile * TILE_N + wn * 64 + tq * 2;

  float sfL[4], sfH[4];
#pragma unroll
  for (int i = 0; i < 4; i++) {
    sfL[i] = rsF[m0 + i * 16];
    sfH[i] = rsF[m0 + i * 16 + 8];
  }

#pragma unroll
  for (int j = 0; j < 8; j++) {
    const float sp0 = rsP[nb + j * 8];
    const float sp1 = rsP[nb + j * 8 + 1];
#pragma unroll
    for (int i = 0; i < 4; i++) {
      const size_t base = (size_t)(m0 + i * 16) * (size_t)Crows + nb + j * 8;
      float2 lo, hi;
      lo.x = -sc * sqrtf(fmaxf(2.0f - 2.0f * ((float)acc[i][j][0] * sfL[i] * sp0), 1e-12f));
      lo.y = -sc * sqrtf(fmaxf(2.0f - 2.0f * ((float)acc[i][j][1] * sfL[i] * sp1), 1e-12f));
      hi.x = -sc * sqrtf(fmaxf(2.0f - 2.0f * ((float)acc[i][j][2] * sfH[i] * sp0), 1e-12f));
      hi.y = -sc * sqrtf(fmaxf(2.0f - 2.0f * ((float)acc[i][j][3] * sfH[i] * sp1), 1e-12f));
      *reinterpret_cast<float2*>(out + base) = lo;
      *reinterpret_cast<float2*>(out + base + 8ull * Crows) = hi;
    }
  }
}

// ------------------------------ launch -----------------------------------
extern "C" void kernel_launch(void* const* d_in, const int* in_sizes, int n_in,
                              void* d_out, int out_size) {
  const float* feats = (const float*)d_in[0];
  const float* prot  = (const float*)d_in[1];
  const float* dsc   = (const float*)d_in[2];
  float* out = (float*)d_out;

  const int N = in_sizes[0] / DDIM;   // 16384
  const int C = in_sizes[1] / DDIM;   // 8192

  void *fnp = nullptr, *pnp = nullptr, *fsp = nullptr, *psp = nullptr;
  cudaGetSymbolAddress(&fnp, g_fn);
  cudaGetSymbolAddress(&pnp, g_pn);
  cudaGetSymbolAddress(&fsp, g_fs);
  cudaGetSymbolAddress(&psp, g_ps);

  norm_pack_kernel<<<N, 256>>>(feats, (char*)fnp, (float*)fsp, TILE_M);
  norm_pack_kernel<<<C, 256>>>(prot, (char*)pnp, (float*)psp, TILE_N);

  cudaFuncSetAttribute(gemm_dist_kernel,
                       cudaFuncAttributeMaxDynamicSharedMemorySize, SMEM_BYTES);
  const int grid = (N / TILE_M) * (C / TILE_N);   // 4096
  gemm_dist_kernel<<<grid, 256, SMEM_BYTES>>>((const char*)fnp, (const char*)pnp,
                                              (const float*)fsp, (const float*)psp,
                                              dsc, out, C);
}

// round 6
// speedup vs baseline: 3.2079x; 3.2079x over previous
#include <cuda_runtime.h>
#include <cuda_bf16.h>
#include <stdint.h>

#define DDIM   2048
#define TILE_M 128
#define TILE_N 256
#define TILE_K 32
#define NKS    (DDIM / TILE_K)      // 64 k-stages
#define STAGES 8
#define NMAX   16384
#define CMAX   8192

#define A_BLK  (TILE_M * TILE_K * 2)   // 8192 bytes per (m-tile, k-stage)
#define B_BLK  (TILE_N * TILE_K * 2)   // 16384 bytes
#define SLOT   (A_BLK + B_BLK)         // 24576
#define SMEM_BYTES (1024 + STAGES * SLOT)   // 197632

// Packed, pre-swizzled bf16 operands (allocation-free scratch)
__device__ __align__(1024) char g_fn[(size_t)NMAX * DDIM * 2];   // 64 MB
__device__ __align__(1024) char g_pn[(size_t)CMAX * DDIM * 2];   // 32 MB

// ------------------------------ PTX helpers -----------------------------
__device__ __forceinline__ uint32_t smem_u32(const void* p) {
  uint32_t a;
  asm("{ .reg .u64 t; cvta.to.shared.u64 t, %1; cvt.u32.u64 %0, t; }" : "=r"(a) : "l"(p));
  return a;
}

#define MBAR_INIT(a, c) asm volatile("mbarrier.init.shared.b64 [%0], %1;" :: "r"(a), "r"(c) : "memory")
#define MBAR_ARRIVE(a)  asm volatile("mbarrier.arrive.shared.b64 _, [%0];" :: "r"(a) : "memory")
#define MBAR_EXPECT_TX(a, n) \
  asm volatile("mbarrier.arrive.expect_tx.shared.b64 _, [%0], %1;" :: "r"(a), "r"(n) : "memory")

#define MBAR_WAIT(a, par) do {                                                              \
  uint32_t _m = (a); uint32_t _p = (par); uint32_t _ok;                                     \
  asm volatile("{\n\t.reg .pred p;\n\t"                                                     \
    "mbarrier.try_wait.parity.acquire.cta.shared::cta.b64 p, [%1], %2;\n\t"                 \
    "selp.b32 %0, 1, 0, p;\n\t}" : "=r"(_ok) : "r"(_m), "r"(_p) : "memory");                \
  if (!_ok) {                                                                               \
    asm volatile("{\n\t.reg .pred P1;\n\t"                                                  \
      "WL_%=:\n\t"                                                                          \
      "mbarrier.try_wait.parity.acquire.cta.shared::cta.b64 P1, [%0], %1, 0x989680;\n\t"    \
      "@P1 bra.uni WD_%=;\n\t"                                                              \
      "bra.uni WL_%=;\n\t"                                                                  \
      "WD_%=:\n\t}" :: "r"(_m), "r"(_p) : "memory");                                        \
  }                                                                                         \
} while (0)

// non-tensor bulk copy gmem -> smem with transaction-count completion (sm_90, non-a)
__device__ __forceinline__ void bulk_g2s(uint32_t dst, const void* src, uint32_t bytes,
                                         uint32_t mbar) {
  asm volatile(
    "cp.async.bulk.shared::cluster.global.mbarrier::complete_tx::bytes [%0], [%1], %2, [%3];"
    :: "r"(dst), "l"(src), "r"(bytes), "r"(mbar) : "memory");
}

__device__ __forceinline__ void ldmx4(uint32_t* r, uint32_t addr) {
  asm volatile("ldmatrix.sync.aligned.m8n8.x4.shared.b16 {%0,%1,%2,%3}, [%4];"
               : "=r"(r[0]), "=r"(r[1]), "=r"(r[2]), "=r"(r[3]) : "r"(addr));
}

__device__ __forceinline__ void mma16816(float* d, const uint32_t* a, uint32_t b0, uint32_t b1) {
  asm volatile(
    "mma.sync.aligned.m16n8k16.row.col.f32.bf16.bf16.f32 "
    "{%0,%1,%2,%3}, {%4,%5,%6,%7}, {%8,%9}, {%0,%1,%2,%3};"
    : "+f"(d[0]), "+f"(d[1]), "+f"(d[2]), "+f"(d[3])
    : "r"(a[0]), "r"(a[1]), "r"(a[2]), "r"(a[3]), "r"(b0), "r"(b1));
}

__device__ __forceinline__ uint32_t bf2_as_u32(__nv_bfloat162 v) {
  return *reinterpret_cast<uint32_t*>(&v);
}

// --------------------------- normalize + pack ---------------------------
// One block per row. Output layout: per (row-tile mt, k-stage kt) a contiguous
// block of tile_rows*64 bytes; inside, row rm holds its 32 bf16 k-slice as 4
// 16B chunks, chunk c stored at c ^ ((rm>>1)&3) (conflict-free for ldmatrix).
__device__ __forceinline__ void pack4(char* rowbase, int t2, float x, float y, float z,
                                      float w, float sc, size_t bstride, uint32_t s) {
  const int kt = t2 >> 3;
  const uint32_t cp = ((uint32_t)t2 & 7) >> 1;
  const uint32_t byo = ((uint32_t)t2 & 1) * 8;
  uint2 v;
  v.x = bf2_as_u32(__floats2bfloat162_rn(x * sc, y * sc));
  v.y = bf2_as_u32(__floats2bfloat162_rn(z * sc, w * sc));
  *reinterpret_cast<uint2*>(rowbase + (size_t)kt * bstride + ((cp ^ s) << 4) + byo) = v;
}

__global__ void norm_pack_kernel(const float* __restrict__ src, char* __restrict__ dst,
                                 int tile_rows) {
  const int row = blockIdx.x;
  const int tid = threadIdx.x;
  const float4* s4 = reinterpret_cast<const float4*>(src + (size_t)row * DDIM);
  float4 v0 = s4[tid];
  float4 v1 = s4[tid + 256];
  float acc = v0.x * v0.x + v0.y * v0.y + v0.z * v0.z + v0.w * v0.w
            + v1.x * v1.x + v1.y * v1.y + v1.z * v1.z + v1.w * v1.w;
#pragma unroll
  for (int o = 16; o > 0; o >>= 1) acc += __shfl_xor_sync(0xFFFFFFFFu, acc, o);
  __shared__ float red[8];
  if ((tid & 31) == 0) red[tid >> 5] = acc;
  __syncthreads();
  float tot = 0.f;
#pragma unroll
  for (int i = 0; i < 8; i++) tot += red[i];
  const float sc = 1.0f / fmaxf(sqrtf(tot), 1e-12f);

  const int mt = row / tile_rows;
  const int rm = row % tile_rows;
  const size_t bstride = (size_t)tile_rows * 64;
  char* rowbase = dst + (size_t)mt * 64 * bstride + (size_t)rm * 64;
  const uint32_t s = ((uint32_t)rm >> 1) & 3;
  pack4(rowbase, tid, v0.x, v0.y, v0.z, v0.w, sc, bstride, s);
  pack4(rowbase, tid + 256, v1.x, v1.y, v1.z, v1.w, sc, bstride, s);
}

// --------------------------- GEMM + distance ----------------------------
// CTA tile 128x256, 8 warps in 2(M) x 4(N), warp tile 64x64, mma m16n8k16 bf16.
__global__ __launch_bounds__(256, 1)
void gemm_dist_kernel(const char* __restrict__ Apk, const char* __restrict__ Bpk,
                      const float* __restrict__ dscale,
                      float* __restrict__ out, int Crows) {
  extern __shared__ __align__(1024) char smem[];
  const uint32_t sb = smem_u32(smem);
  const int tid = threadIdx.x;
  const int wid = tid >> 5;
  const int lane = tid & 31;

  // supertile mapping: groups of 4 m-tiles x all n-tiles keep B L2-resident
  const int nt = Crows / TILE_N;                 // 32
  const int per_sg = 4 * nt;                     // 128
  const int sg = blockIdx.x / per_sg;
  const int r = blockIdx.x % per_sg;
  const int m_tile = sg * 4 + (r & 3);
  const int n_tile = r >> 2;

  const char* Abase = Apk + (size_t)m_tile * NKS * A_BLK;
  const char* Bbase = Bpk + (size_t)n_tile * NKS * B_BLK;

  // barriers: full[s] @ sb + s*8 ; empty[s] @ sb + 128 + s*8
  if (tid == 0) {
#pragma unroll
    for (int s = 0; s < STAGES; s++) {
      MBAR_INIT(sb + s * 8, 1);
      MBAR_INIT(sb + 128 + s * 8, 8);
    }
  }
  __syncthreads();

  // producer prologue: stages 0..STAGES-2
  if (tid == 0) {
#pragma unroll
    for (int t = 0; t < STAGES - 1; t++) {
      const uint32_t full = sb + t * 8;
      const uint32_t slot = sb + 1024 + t * SLOT;
      MBAR_EXPECT_TX(full, SLOT);
      bulk_g2s(slot, Abase + (size_t)t * A_BLK, A_BLK, full);
      bulk_g2s(slot + A_BLK, Bbase + (size_t)t * B_BLK, B_BLK, full);
    }
  }

  // per-lane ldmatrix addressing constants
  const int wm = wid & 1;
  const int wn = wid >> 1;
  const uint32_t sA = (((uint32_t)lane & 15) >> 1) & 3;
  const uint32_t sB = (((uint32_t)lane & 7) >> 1) & 3;
  const uint32_t aRowOff = (uint32_t)(wm * 64 + (lane & 15)) * 64;
  const uint32_t aChunkHalf = (uint32_t)(lane >> 4);
  const uint32_t bRowOff = (uint32_t)(wn * 64 + (lane >> 4) * 8 + (lane & 7)) * 64;
  const uint32_t bChunkHalf = ((uint32_t)lane >> 3) & 1;

  float acc[4][8][4];
#pragma unroll
  for (int i = 0; i < 4; i++)
#pragma unroll
    for (int j = 0; j < 8; j++)
#pragma unroll
      for (int c = 0; c < 4; c++) acc[i][j][c] = 0.f;

  for (int i = 0; i < NKS; i++) {
    const int t = i + STAGES - 1;
    if (t < NKS && tid == 0) {
      const int ts = t % STAGES;
      MBAR_WAIT(sb + 128 + ts * 8, ((t / STAGES) - 1) & 1);     // slot free
      const uint32_t full = sb + ts * 8;
      const uint32_t slot = sb + 1024 + ts * SLOT;
      MBAR_EXPECT_TX(full, SLOT);
      bulk_g2s(slot, Abase + (size_t)t * A_BLK, A_BLK, full);
      bulk_g2s(slot + A_BLK, Bbase + (size_t)t * B_BLK, B_BLK, full);
    }

    const int is = i % STAGES;
    MBAR_WAIT(sb + is * 8, (i / STAGES) & 1);                   // data ready
    const uint32_t slot = sb + 1024 + is * SLOT;

    // front-batch ALL ldmatrix for this stage (both k-halves), then run
    // 64 independent MMAs back-to-back: LDSM latency hides behind the other
    // warp's MMA stream, and the MMA stream itself has no smem dependency.
    uint32_t a[2][4][4], b[2][4][4];
#pragma unroll
    for (int ks = 0; ks < 2; ks++) {
      const uint32_t ca = (((uint32_t)ks * 2 + aChunkHalf) ^ sA) << 4;
      const uint32_t cb = (((uint32_t)ks * 2 + bChunkHalf) ^ sB) << 4;
#pragma unroll
      for (int ii = 0; ii < 4; ii++) ldmx4(a[ks][ii], slot + aRowOff + ii * 1024 + ca);
#pragma unroll
      for (int jp = 0; jp < 4; jp++) ldmx4(b[ks][jp], slot + A_BLK + bRowOff + jp * 1024 + cb);
    }

#pragma unroll
    for (int ks = 0; ks < 2; ks++)
#pragma unroll
      for (int ii = 0; ii < 4; ii++)
#pragma unroll
        for (int j = 0; j < 8; j++)
          mma16816(acc[ii][j], a[ks][ii],
                   b[ks][j >> 1][(j & 1) * 2], b[ks][j >> 1][(j & 1) * 2 + 1]);

    if (lane == 0) MBAR_ARRIVE(sb + 128 + is * 8);              // slot consumed
  }

  // fused distance epilogue
  const float sc = fabsf(dscale[0]);
  const int g = lane >> 2;
  const int tq = lane & 3;
  const int m0 = m_tile * TILE_M + wm * 64 + g;
  const int n0 = n_tile * TILE_N + wn * 64 + tq * 2;

#pragma unroll
  for (int i = 0; i < 4; i++) {
#pragma unroll
    for (int j = 0; j < 8; j++) {
      const size_t base = (size_t)(m0 + i * 16) * (size_t)Crows + n0 + j * 8;
      float2 lo, hi;
      lo.x = -sc * sqrtf(fmaxf(2.0f - 2.0f * acc[i][j][0], 1e-12f));
      lo.y = -sc * sqrtf(fmaxf(2.0f - 2.0f * acc[i][j][1], 1e-12f));
      hi.x = -sc * sqrtf(fmaxf(2.0f - 2.0f * acc[i][j][2], 1e-12f));
      hi.y = -sc * sqrtf(fmaxf(2.0f - 2.0f * acc[i][j][3], 1e-12f));
      *reinterpret_cast<float2*>(out + base) = lo;
      *reinterpret_cast<float2*>(out + base + 8ull * Crows) = hi;
    }
  }
}

// ------------------------------ launch -----------------------------------
extern "C" void kernel_launch(void* const* d_in, const int* in_sizes, int n_in,
                              void* d_out, int out_size) {
  const float* feats = (const float*)d_in[0];
  const float* prot  = (const float*)d_in[1];
  const float* dsc   = (const float*)d_in[2];
  float* out = (float*)d_out;

  const int N = in_sizes[0] / DDIM;   // 16384
  const int C = in_sizes[1] / DDIM;   // 8192

  void *fnp = nullptr, *pnp = nullptr;
  cudaGetSymbolAddress(&fnp, g_fn);
  cudaGetSymbolAddress(&pnp, g_pn);

  norm_pack_kernel<<<N, 256>>>(feats, (char*)fnp, TILE_M);
  norm_pack_kernel<<<C, 256>>>(prot, (char*)pnp, TILE_N);

  cudaFuncSetAttribute(gemm_dist_kernel,
                       cudaFuncAttributeMaxDynamicSharedMemorySize, SMEM_BYTES);
  const int grid = (N / TILE_M) * (C / TILE_N);   // 4096
  gemm_dist_kernel<<<grid, 256, SMEM_BYTES>>>((const char*)fnp, (const char*)pnp,
                                              dsc, out, C);
}